// round 1
// baseline (speedup 1.0000x reference)
#include <cuda_runtime.h>
#include <math.h>

#define BATCH 256
#define TLEN  50
#define NOBS  8192
#define NKC   50

// ---- device-global scratch (no allocations allowed) ----
__device__ unsigned int g_assign_u32[NOBS / 4];   // assign[] packed as uint8
__device__ float        g_probs[NKC * 5];          // sigmoid(kc_logits)
__device__ float        g_compact[BATCH * NKC];    // compact per-KC state
__device__ float        g_probs_scratch[BATCH * TLEN]; // fallback sink

// ============================================================
// k1: recover assign[] from one-hot A (coalesced scan over all
// 409600 elements; exactly one element per row is 1.0), and
// compute probs_kc = sigmoid(kc_logits).
// ============================================================
__global__ void k1_prep(const float* __restrict__ A,
                        const float* __restrict__ kc_logits) {
    int i = blockIdx.x * blockDim.x + threadIdx.x;
    if (i < NOBS * NKC) {
        if (A[i] > 0.5f) {
            int o = i / NKC;
            int k = i - o * NKC;
            ((unsigned char*)g_assign_u32)[o] = (unsigned char)k;
        }
    }
    if (i < NKC * 5) {
        g_probs[i] = 1.0f / (1.0f + expf(-kc_logits[i]));
    }
}

// ============================================================
// k2: the BKT recurrence. One thread per batch row.
// Compact state in shared, laid out [k][tid] -> bank-conflict free.
// assign (u8) and probs_kc staged in shared so the per-step
// dependent chain is shared-latency only.
// ============================================================
__global__ __launch_bounds__(128, 1)
void k2_recur(const int*   __restrict__ prev_kc,
              const int*   __restrict__ curr_kc,
              const float* __restrict__ prev_corr,
              float*       __restrict__ probs_out) {
    __shared__ float         s_state[NKC][128];
    __shared__ float         s_probs[NKC * 5];
    __shared__ unsigned int  s_assign[NOBS / 4];

    const int tid = threadIdx.x;

    for (int i = tid; i < NOBS / 4; i += 128) s_assign[i] = g_assign_u32[i];
    for (int i = tid; i < NKC * 5;  i += 128) s_probs[i]  = g_probs[i];
    __syncthreads();

    const unsigned char* s_as = (const unsigned char*)s_assign;

    const int b = blockIdx.x * 128 + tid;
    const int*   pkp  = prev_kc   + b * TLEN;
    const int*   ckp  = curr_kc   + b * TLEN;
    const float* corp = prev_corr + b * TLEN;
    float*       out  = probs_out + b * TLEN;

    // state0[k] = probs_kc[k][4]
    #pragma unroll
    for (int k = 0; k < NKC; k++) s_state[k][tid] = s_probs[k * 5 + 4];

    // t = 0: prediction only
    {
        int   ck = ckp[0];
        int   ac = s_as[ck];
        float cs = s_state[ac][tid];
        out[0] = s_probs[ac * 5 + 2] * (1.0f - cs) + s_probs[ac * 5 + 3] * cs;
    }

    for (int t = 1; t < TLEN; t++) {
        int   pk  = pkp[t];
        int   ck  = ckp[t];
        float pcr = corp[t];

        int   ap = s_as[pk];
        float pl = s_probs[ap * 5 + 0];  // p_learn
        float pf = s_probs[ap * 5 + 1];  // p_forget
        float p2 = s_probs[ap * 5 + 2];
        float p3 = s_probs[ap * 5 + 3];

        // p_out = pch^pcorr * (1-pch)^(1-pcorr), pcorr in {0,1}
        float o0 = (pcr > 0.5f) ? p2 : (1.0f - p2);
        float o1 = (pcr > 0.5f) ? p3 : (1.0f - p3);

        float ss   = s_state[ap][tid];
        float num  = o1 * ss;
        float filt = num / (o0 * (1.0f - ss) + num);
        float pred = pl * (1.0f - filt) + (1.0f - pf) * filt;
        s_state[ap][tid] = pred;

        int   ac = s_as[ck];
        float cs = s_state[ac][tid];   // same-thread store->load, ordered
        out[t] = s_probs[ac * 5 + 2] * (1.0f - cs) + s_probs[ac * 5 + 3] * cs;
    }

    // hand compact state to k3
    #pragma unroll
    for (int k = 0; k < NKC; k++) g_compact[b * NKC + k] = s_state[k][tid];
}

// ============================================================
// k3: expand compact state to (B, N_OBS): state[b,o] = compact[b, assign[o]].
// uchar4 assign reads, float4 coalesced stores. One block per batch row.
// ============================================================
__global__ __launch_bounds__(256)
void k3_expand(float* __restrict__ state_out) {
    const int b   = blockIdx.x;
    const int tid = threadIdx.x;

    __shared__ float row[NKC];
    if (tid < NKC) row[tid] = g_compact[b * NKC + tid];
    __syncthreads();

    float4*       out = (float4*)(state_out + (size_t)b * NOBS);
    const uchar4* as4 = (const uchar4*)g_assign_u32;

    #pragma unroll
    for (int i = tid; i < NOBS / 4; i += 256) {
        uchar4 a = as4[i];
        out[i] = make_float4(row[a.x], row[a.y], row[a.z], row[a.w]);
    }
}

// ============================================================
extern "C" void kernel_launch(void* const* d_in, const int* in_sizes, int n_in,
                              void* d_out, int out_size) {
    const int*   prev_kc   = (const int*)  d_in[0];
    const int*   curr_kc   = (const int*)  d_in[1];
    const float* prev_corr = (const float*)d_in[2];
    const float* kc_logits = (const float*)d_in[3];
    const float* A         = (const float*)d_in[4];
    float*       out       = (float*)d_out;

    k1_prep<<<(NOBS * NKC + 255) / 256, 256>>>(A, kc_logits);

    // Output layout: expected [probs (256*50) | state (256*8192)] concatenated.
    // Defensive branches in case the harness exposes only one of them.
    float* probs_out = out;
    float* state_out = out + BATCH * TLEN;
    bool   do_state  = true;

    if (out_size == BATCH * TLEN) {
        // probs only
        do_state = false;
    } else if (out_size == BATCH * NOBS) {
        // state only; route probs to scratch
        void* scratch = nullptr;
        cudaGetSymbolAddress(&scratch, g_probs_scratch);
        probs_out = (float*)scratch;
        state_out = out;
    }

    k2_recur<<<BATCH / 128, 128>>>(prev_kc, curr_kc, prev_corr, probs_out);

    if (do_state) {
        k3_expand<<<BATCH, 256>>>(state_out);
    }
}

// round 2
// speedup vs baseline: 1.1160x; 1.1160x over previous
#include <cuda_runtime.h>
#include <math.h>

#define BATCH 256
#define TLEN  50
#define NOBS  8192
#define NKC   50

// ---- device-global scratch (no allocations allowed) ----
__device__ unsigned char g_assign[NOBS];          // assign[] as uint8
__device__ float         g_probs[NKC * 5];         // sigmoid(kc_logits)
__device__ float         g_compact[BATCH * NKC];   // compact per-KC state
__device__ float         g_probs_scratch[BATCH * TLEN]; // fallback sink

// ============================================================
// k1: recover assign[] from one-hot A (float4 grid-stride, MLP>=4)
// and compute probs_kc = sigmoid(kc_logits).
// ============================================================
__global__ __launch_bounds__(256)
void k1_prep(const float4* __restrict__ A4,
             const float*  __restrict__ kc_logits) {
    const int n4 = NOBS * NKC / 4;
    int j = blockIdx.x * blockDim.x + threadIdx.x;

    for (int idx = j; idx < n4; idx += gridDim.x * blockDim.x) {
        float4 v = A4[idx];
        int base = idx * 4;
        if (v.x > 0.5f) { int i = base + 0; g_assign[i / NKC] = (unsigned char)(i % NKC); }
        if (v.y > 0.5f) { int i = base + 1; g_assign[i / NKC] = (unsigned char)(i % NKC); }
        if (v.z > 0.5f) { int i = base + 2; g_assign[i / NKC] = (unsigned char)(i % NKC); }
        if (v.w > 0.5f) { int i = base + 3; g_assign[i / NKC] = (unsigned char)(i % NKC); }
    }

    if (j < NKC * 5) {
        g_probs[j] = 1.0f / (1.0f + expf(-kc_logits[j]));
    }
}

// ============================================================
// k2: BKT recurrence. One thread per batch row (2 blocks x 128).
// All loop-body operands pre-resolved into shared; per-thread
// private state column in shared [k][tid] (conflict-free).
// s_state doubles as the coalesced staging buffer before init.
// ============================================================
__global__ __launch_bounds__(128, 1)
void k2_recur(const int*   __restrict__ prev_kc,
              const int*   __restrict__ curr_kc,
              const float* __restrict__ prev_corr,
              float*       __restrict__ probs_out) {
    __shared__ float         s_state[NKC * 128];   // 25.6 KB (staging union)
    __shared__ float4        s_pr[NKC];            // p0..p3 packed
    __shared__ float         s_p4[NKC];            // initial state
    __shared__ unsigned char s_apk[TLEN * 128];    // assign[pk] | corr<<7
    __shared__ unsigned char s_ack[TLEN * 128];    // assign[ck]

    const int tid = threadIdx.x;
    const int b0  = blockIdx.x * 128;
    const int b   = b0 + tid;

    if (tid < NKC) {
        float4 p;
        p.x = g_probs[tid * 5 + 0];
        p.y = g_probs[tid * 5 + 1];
        p.z = g_probs[tid * 5 + 2];
        p.w = g_probs[tid * 5 + 3];
        s_pr[tid] = p;
        s_p4[tid] = g_probs[tid * 5 + 4];
    }

    int*   raw  = (int*)s_state;
    float* rawf = s_state;

    // --- stage prev_kc (coalesced) -> resolve assign ---
    for (int i = tid; i < TLEN * 128; i += 128) raw[i] = prev_kc[b0 * TLEN + i];
    __syncthreads();
    #pragma unroll
    for (int t = 0; t < TLEN; t++)
        s_apk[t * 128 + tid] = g_assign[raw[tid * TLEN + t]];
    __syncthreads();

    // --- stage curr_kc -> resolve assign ---
    for (int i = tid; i < TLEN * 128; i += 128) raw[i] = curr_kc[b0 * TLEN + i];
    __syncthreads();
    #pragma unroll
    for (int t = 0; t < TLEN; t++)
        s_ack[t * 128 + tid] = g_assign[raw[tid * TLEN + t]];
    __syncthreads();

    // --- stage prev_corr -> fold correctness bit into s_apk ---
    for (int i = tid; i < TLEN * 128; i += 128) rawf[i] = prev_corr[b0 * TLEN + i];
    __syncthreads();
    #pragma unroll
    for (int t = 1; t < TLEN; t++)
        if (rawf[tid * TLEN + t] > 0.5f) s_apk[t * 128 + tid] |= 0x80;
    __syncthreads();

    // --- init private state column ---
    #pragma unroll
    for (int k = 0; k < NKC; k++) s_state[k * 128 + tid] = s_p4[k];

    float* out = probs_out + b * TLEN;

    // t = 0: prediction only
    {
        int    ac = s_ack[tid];
        float  cs = s_state[ac * 128 + tid];
        float4 pc = s_pr[ac];
        out[0] = fmaf(pc.w - pc.z, cs, pc.z);       // p2*(1-cs)+p3*cs
    }

    #pragma unroll
    for (int t = 1; t < TLEN; t++) {
        unsigned int af = s_apk[t * 128 + tid];
        int    ap = af & 0x7f;
        float4 pp = s_pr[ap];
        float  ss = s_state[ap * 128 + tid];

        float o0, o1;
        if (af & 0x80u) { o0 = pp.z;        o1 = pp.w;        }
        else            { o0 = 1.0f - pp.z; o1 = 1.0f - pp.w; }

        float num  = o1 * ss;
        float den  = fmaf(o0, 1.0f - ss, num);
        float filt = __fdividef(num, den);
        // p_learn*(1-filt) + (1-p_forget)*filt
        float pred = fmaf(1.0f - pp.y - pp.x, filt, pp.x);
        s_state[ap * 128 + tid] = pred;

        int    ac = s_ack[t * 128 + tid];
        float  cs = s_state[ac * 128 + tid];
        float4 pc = s_pr[ac];
        out[t] = fmaf(pc.w - pc.z, cs, pc.z);
    }

    // hand compact state to k3
    #pragma unroll
    for (int k = 0; k < NKC; k++) g_compact[b * NKC + k] = s_state[k * 128 + tid];
}

// ============================================================
// k3: expand compact state to (B, N_OBS): state[b,o] = compact[b, assign[o]].
// uchar4 assign reads (L2-hot), float4 coalesced stores (8 MB).
// ============================================================
__global__ __launch_bounds__(512)
void k3_expand(float* __restrict__ state_out) {
    const int b   = blockIdx.x;
    const int tid = threadIdx.x;

    __shared__ float row[NKC];
    if (tid < NKC) row[tid] = g_compact[b * NKC + tid];
    __syncthreads();

    float4*       out = (float4*)(state_out + (size_t)b * NOBS);
    const uchar4* as4 = (const uchar4*)g_assign;

    #pragma unroll
    for (int i = tid; i < NOBS / 4; i += 512) {
        uchar4 a = as4[i];
        out[i] = make_float4(row[a.x], row[a.y], row[a.z], row[a.w]);
    }
}

// ============================================================
extern "C" void kernel_launch(void* const* d_in, const int* in_sizes, int n_in,
                              void* d_out, int out_size) {
    const int*    prev_kc   = (const int*)   d_in[0];
    const int*    curr_kc   = (const int*)   d_in[1];
    const float*  prev_corr = (const float*) d_in[2];
    const float*  kc_logits = (const float*) d_in[3];
    const float4* A4        = (const float4*)d_in[4];
    float*        out       = (float*)d_out;

    k1_prep<<<160, 256>>>(A4, kc_logits);

    // Output layout: [probs (256*50) | state (256*8192)] concatenated.
    float* probs_out = out;
    float* state_out = out + BATCH * TLEN;
    bool   do_state  = true;

    if (out_size == BATCH * TLEN) {
        do_state = false;
    } else if (out_size == BATCH * NOBS) {
        void* scratch = nullptr;
        cudaGetSymbolAddress(&scratch, g_probs_scratch);
        probs_out = (float*)scratch;
        state_out = out;
    }

    k2_recur<<<BATCH / 128, 128>>>(prev_kc, curr_kc, prev_corr, probs_out);

    if (do_state) {
        k3_expand<<<BATCH, 512>>>(state_out);
    }
}

// round 3
// speedup vs baseline: 1.5563x; 1.3944x over previous
#include <cuda_runtime.h>
#include <math.h>

#define BATCH 256
#define TLEN  50
#define NOBS  8192
#define NKC   50

// ---- device-global scratch (no allocations allowed) ----
__device__ unsigned char g_assign[NOBS];                 // assign[] as uint8
__device__ float         g_compact[BATCH * NKC];         // compact per-KC state
__device__ float         g_probs_scratch[BATCH * TLEN];  // fallback sink

// ============================================================
// k1: recover assign[] from one-hot A. One float4 per thread,
// full-chip grid (102400 threads) -> pure bandwidth, no loop.
// ============================================================
__global__ __launch_bounds__(256)
void k1_prep(const float4* __restrict__ A4) {
    int idx = blockIdx.x * 256 + threadIdx.x;     // < NOBS*NKC/4 = 102400
    float4 v = A4[idx];
    int base = idx * 4;
    if (v.x > 0.5f) { int i = base + 0; g_assign[i / NKC] = (unsigned char)(i % NKC); }
    if (v.y > 0.5f) { int i = base + 1; g_assign[i / NKC] = (unsigned char)(i % NKC); }
    if (v.z > 0.5f) { int i = base + 2; g_assign[i / NKC] = (unsigned char)(i % NKC); }
    if (v.w > 0.5f) { int i = base + 3; g_assign[i / NKC] = (unsigned char)(i % NKC); }
}

// ============================================================
// k2: BKT recurrence. One thread per batch row (2 blocks x 128).
// Prologue: fully-unrolled per-thread register loads (MLP~50 per
// phase, no syncs, phases overlap via scoreboard), gathers of
// g_assign resolved into u8 shared tables. Sigmoid computed
// locally. Main loop touches only shared memory.
// ============================================================
__global__ __launch_bounds__(128, 1)
void k2_recur(const int*   __restrict__ prev_kc,
              const int*   __restrict__ curr_kc,
              const float* __restrict__ prev_corr,
              const float* __restrict__ kc_logits,
              float*       __restrict__ probs_out) {
    __shared__ float         s_state[NKC * 128];   // 25.6 KB, [k][tid]
    __shared__ float4        s_pr[NKC];            // p0..p3 (sigmoid)
    __shared__ float         s_p4[NKC];            // initial state
    __shared__ unsigned char s_apk[TLEN * 128];    // assign[pk] | corr<<7
    __shared__ unsigned char s_ack[TLEN * 128];    // assign[ck]

    const int tid = threadIdx.x;
    const int b   = blockIdx.x * 128 + tid;

    // local sigmoid of kc_logits (250 values, off critical path)
    if (tid < NKC) {
        float4 p;
        p.x = 1.0f / (1.0f + __expf(-kc_logits[tid * 5 + 0]));
        p.y = 1.0f / (1.0f + __expf(-kc_logits[tid * 5 + 1]));
        p.z = 1.0f / (1.0f + __expf(-kc_logits[tid * 5 + 2]));
        p.w = 1.0f / (1.0f + __expf(-kc_logits[tid * 5 + 3]));
        s_pr[tid] = p;
        s_p4[tid] = 1.0f / (1.0f + __expf(-kc_logits[tid * 5 + 4]));
    }

    const int*   pkp  = prev_kc   + b * TLEN;
    const int*   ckp  = curr_kc   + b * TLEN;
    const float* corp = prev_corr + b * TLEN;

    // phase 1: pull pk + corr into registers (100 independent LDGs)
    int   pk[TLEN];
    float cr[TLEN];
    #pragma unroll
    for (int t = 0; t < TLEN; t++) pk[t] = pkp[t];
    #pragma unroll
    for (int t = 0; t < TLEN; t++) cr[t] = corp[t];

    // phase 2: resolve assign[pk] | corr bit  (50 byte-gathers, MLP=50)
    #pragma unroll
    for (int t = 0; t < TLEN; t++)
        s_apk[t * 128 + tid] =
            g_assign[pk[t]] | (cr[t] > 0.5f ? (unsigned char)0x80 : (unsigned char)0);

    // phase 3: ck loads + gathers
    int ck[TLEN];
    #pragma unroll
    for (int t = 0; t < TLEN; t++) ck[t] = ckp[t];
    #pragma unroll
    for (int t = 0; t < TLEN; t++)
        s_ack[t * 128 + tid] = g_assign[ck[t]];

    __syncthreads();   // s_pr / s_p4 visible

    // init private state column
    #pragma unroll
    for (int k = 0; k < NKC; k++) s_state[k * 128 + tid] = s_p4[k];

    float* out = probs_out + b * TLEN;

    // t = 0: prediction only
    {
        int    ac = s_ack[tid];
        float  cs = s_state[ac * 128 + tid];
        float4 pc = s_pr[ac];
        out[0] = fmaf(pc.w - pc.z, cs, pc.z);       // p2*(1-cs)+p3*cs
    }

    #pragma unroll
    for (int t = 1; t < TLEN; t++) {
        unsigned int af = s_apk[t * 128 + tid];
        int    ap = af & 0x7f;
        float4 pp = s_pr[ap];
        float  ss = s_state[ap * 128 + tid];

        float o0, o1;
        if (af & 0x80u) { o0 = pp.z;        o1 = pp.w;        }
        else            { o0 = 1.0f - pp.z; o1 = 1.0f - pp.w; }

        float num  = o1 * ss;
        float den  = fmaf(o0, 1.0f - ss, num);
        float filt = __fdividef(num, den);
        float pred = fmaf(1.0f - pp.y - pp.x, filt, pp.x);  // pl*(1-f)+(1-pf)*f
        s_state[ap * 128 + tid] = pred;

        int    ac = s_ack[t * 128 + tid];
        float  cs = s_state[ac * 128 + tid];
        float4 pc = s_pr[ac];
        out[t] = fmaf(pc.w - pc.z, cs, pc.z);
    }

    // hand compact state to k3
    #pragma unroll
    for (int k = 0; k < NKC; k++) g_compact[b * NKC + k] = s_state[k * 128 + tid];
}

// ============================================================
// k3: expand compact state: state[b,o] = compact[b, assign[o]].
// uchar4 assign reads (L2-hot), float4 coalesced stores (8 MB).
// ============================================================
__global__ __launch_bounds__(512)
void k3_expand(float* __restrict__ state_out) {
    const int b   = blockIdx.x;
    const int tid = threadIdx.x;

    __shared__ float row[NKC];
    if (tid < NKC) row[tid] = g_compact[b * NKC + tid];
    __syncthreads();

    float4*       out = (float4*)(state_out + (size_t)b * NOBS);
    const uchar4* as4 = (const uchar4*)g_assign;

    #pragma unroll
    for (int i = tid; i < NOBS / 4; i += 512) {
        uchar4 a = as4[i];
        out[i] = make_float4(row[a.x], row[a.y], row[a.z], row[a.w]);
    }
}

// ============================================================
extern "C" void kernel_launch(void* const* d_in, const int* in_sizes, int n_in,
                              void* d_out, int out_size) {
    const int*    prev_kc   = (const int*)   d_in[0];
    const int*    curr_kc   = (const int*)   d_in[1];
    const float*  prev_corr = (const float*) d_in[2];
    const float*  kc_logits = (const float*) d_in[3];
    const float4* A4        = (const float4*)d_in[4];
    float*        out       = (float*)d_out;

    k1_prep<<<(NOBS * NKC / 4) / 256, 256>>>(A4);

    // Output layout: [probs (256*50) | state (256*8192)] concatenated.
    float* probs_out = out;
    float* state_out = out + BATCH * TLEN;
    bool   do_state  = true;

    if (out_size == BATCH * TLEN) {
        do_state = false;
    } else if (out_size == BATCH * NOBS) {
        void* scratch = nullptr;
        cudaGetSymbolAddress(&scratch, g_probs_scratch);
        probs_out = (float*)scratch;
        state_out = out;
    }

    k2_recur<<<BATCH / 128, 128>>>(prev_kc, curr_kc, prev_corr, kc_logits, probs_out);

    if (do_state) {
        k3_expand<<<BATCH, 512>>>(state_out);
    }
}

// round 4
// speedup vs baseline: 3.0852x; 1.9825x over previous
#include <cuda_runtime.h>
#include <math.h>

#define BATCH 256
#define TLEN  50
#define NOBS  8192
#define NKC   50

// ---- device-global scratch (no allocations allowed) ----
__device__ unsigned char g_assign[NOBS];                 // assign[] as uint8
__device__ float         g_probs_scratch[BATCH * TLEN];  // fallback sink

// ============================================================
// k1: recover assign[] from one-hot A. One float4 per thread,
// full-chip grid (102400 threads).
// ============================================================
__global__ __launch_bounds__(256)
void k1_prep(const float4* __restrict__ A4) {
    int idx = blockIdx.x * 256 + threadIdx.x;     // < NOBS*NKC/4 = 102400
    float4 v = A4[idx];
    int base = idx * 4;
    if (v.x > 0.5f) { int i = base + 0; g_assign[i / NKC] = (unsigned char)(i % NKC); }
    if (v.y > 0.5f) { int i = base + 1; g_assign[i / NKC] = (unsigned char)(i % NKC); }
    if (v.z > 0.5f) { int i = base + 2; g_assign[i / NKC] = (unsigned char)(i % NKC); }
    if (v.w > 0.5f) { int i = base + 3; g_assign[i / NKC] = (unsigned char)(i % NKC); }
}

// ============================================================
// k2: fused recurrence + state expansion. ONE BLOCK PER BATCH ROW
// (256 blocks x 128 threads) so input loading / gathering /
// expansion are spread across the whole chip; the only serial
// part is the 49-step scalar chain run by thread 0 per block,
// entirely in shared memory.
// ============================================================
__global__ __launch_bounds__(128, 8)
void k2_fused(const int*   __restrict__ prev_kc,
              const int*   __restrict__ curr_kc,
              const float* __restrict__ prev_corr,
              const float* __restrict__ kc_logits,
              float*       __restrict__ probs_out,
              float*       __restrict__ state_out,
              int do_state) {
    __shared__ unsigned char s_assign[NOBS];   // 8 KB
    __shared__ float4        s_pr[NKC];        // sigmoid(p0..p3)
    __shared__ float         s_state[NKC];     // compact state (one row)
    __shared__ unsigned char s_apk[TLEN];      // assign[pk] | corr<<7
    __shared__ unsigned char s_ack[TLEN];      // assign[ck]

    const int b   = blockIdx.x;
    const int tid = threadIdx.x;

    // --- copy g_assign -> shared, 4 x int4 per thread (coalesced, L2-hot) ---
    {
        const int4* src = (const int4*)g_assign;
        int4*       dst = (int4*)s_assign;
        #pragma unroll
        for (int i = 0; i < 4; i++) dst[tid + 128 * i] = src[tid + 128 * i];
    }

    // --- row inputs + sigmoids (threads 0..49), loads overlap the copy ---
    int   pk = 0, ck = 0;
    float cr = 0.0f;
    if (tid < TLEN) {
        pk = prev_kc[b * TLEN + tid];
        ck = curr_kc[b * TLEN + tid];
        cr = prev_corr[b * TLEN + tid];

        float4 p;
        p.x = 1.0f / (1.0f + __expf(-kc_logits[tid * 5 + 0]));
        p.y = 1.0f / (1.0f + __expf(-kc_logits[tid * 5 + 1]));
        p.z = 1.0f / (1.0f + __expf(-kc_logits[tid * 5 + 2]));
        p.w = 1.0f / (1.0f + __expf(-kc_logits[tid * 5 + 3]));
        s_pr[tid]    = p;
        s_state[tid] = 1.0f / (1.0f + __expf(-kc_logits[tid * 5 + 4]));
    }
    __syncthreads();   // s_assign complete

    // --- resolve index tables from SHARED (LDS gathers, cheap) ---
    if (tid < TLEN) {
        s_apk[tid] = s_assign[pk] | (cr > 0.5f ? (unsigned char)0x80 : (unsigned char)0);
        s_ack[tid] = s_assign[ck];
    }
    __syncthreads();

    // --- serial recurrence: thread 0 only ---
    if (tid == 0) {
        float* out = probs_out + b * TLEN;
        {
            int    ac = s_ack[0];
            float  cs = s_state[ac];
            float4 pc = s_pr[ac];
            out[0] = fmaf(pc.w - pc.z, cs, pc.z);        // p2*(1-cs)+p3*cs
        }
        #pragma unroll
        for (int t = 1; t < TLEN; t++) {
            unsigned int af = s_apk[t];
            int    ap = af & 0x7f;
            float4 pp = s_pr[ap];
            float  ss = s_state[ap];

            float o0, o1;
            if (af & 0x80u) { o0 = pp.z;        o1 = pp.w;        }
            else            { o0 = 1.0f - pp.z; o1 = 1.0f - pp.w; }

            float num  = o1 * ss;
            float filt = __fdividef(num, fmaf(o0, 1.0f - ss, num));
            float pred = fmaf(1.0f - pp.y - pp.x, filt, pp.x);   // pl*(1-f)+(1-pf)*f
            s_state[ap] = pred;

            int    ac = s_ack[t];
            float  cs = s_state[ac];     // same-thread store->load, ordered
            float4 pc = s_pr[ac];
            out[t] = fmaf(pc.w - pc.z, cs, pc.z);
        }
    }
    __syncthreads();   // final state visible to all threads

    // --- expand final state to (1, NOBS): 16 float4 stores per thread ---
    if (do_state) {
        float4*       o  = (float4*)(state_out + (size_t)b * NOBS);
        const uchar4* a4 = (const uchar4*)s_assign;
        #pragma unroll
        for (int i = 0; i < 16; i++) {
            uchar4 a = a4[tid + 128 * i];
            o[tid + 128 * i] =
                make_float4(s_state[a.x], s_state[a.y], s_state[a.z], s_state[a.w]);
        }
    }
}

// ============================================================
extern "C" void kernel_launch(void* const* d_in, const int* in_sizes, int n_in,
                              void* d_out, int out_size) {
    const int*    prev_kc   = (const int*)   d_in[0];
    const int*    curr_kc   = (const int*)   d_in[1];
    const float*  prev_corr = (const float*) d_in[2];
    const float*  kc_logits = (const float*) d_in[3];
    const float4* A4        = (const float4*)d_in[4];
    float*        out       = (float*)d_out;

    k1_prep<<<(NOBS * NKC / 4) / 256, 256>>>(A4);

    // Output layout: [probs (256*50) | state (256*8192)] concatenated.
    float* probs_out = out;
    float* state_out = out + BATCH * TLEN;
    int    do_state  = 1;

    if (out_size == BATCH * TLEN) {
        do_state  = 0;
        state_out = out;                 // unused
    } else if (out_size == BATCH * NOBS) {
        void* scratch = nullptr;
        cudaGetSymbolAddress(&scratch, g_probs_scratch);
        probs_out = (float*)scratch;
        state_out = out;
    }

    k2_fused<<<BATCH, 128>>>(prev_kc, curr_kc, prev_corr, kc_logits,
                             probs_out, state_out, do_state);
}